// round 1
// baseline (speedup 1.0000x reference)
#include <cuda_runtime.h>
#include <math.h>

#define TS 32
#define NT 256
#define IN_DIM 40   // TS + 2*4 halo
#define TMP_W 36    // after horizontal gauss (x halo 4 -> 2)
#define BLUR_DIM 36 // y halo 2, x halo 2
#define GM_DIM 34   // grad-mag with halo 1 for NMS

__global__ __launch_bounds__(NT) void canny_fused_kernel(
    const float* __restrict__ img, float* __restrict__ out,
    int H, int W)
{
    __shared__ float s_in[IN_DIM][IN_DIM + 1];
    __shared__ float s_tmp[IN_DIM][TMP_W + 1];
    __shared__ float s_blur[BLUR_DIM][BLUR_DIM + 1];
    __shared__ float s_gmag[GM_DIM][GM_DIM + 1];
    __shared__ float s_sgx[TS][TS];
    __shared__ float s_sgy[TS][TS];

    const int tid = threadIdx.x;
    const int x0 = blockIdx.x * TS;
    const int y0 = blockIdx.y * TS;
    const int b  = blockIdx.z;

    // scipy.signal.gaussian(5, std=1): unnormalized, peak 1 (fp32 of fp64 exp)
    const float G0 = 0.13533528f;   // exp(-2)
    const float G1 = 0.60653067f;   // exp(-0.5)

    for (int c = 0; c < 3; ++c) {
        const float* ch = img + ((size_t)(b * 3 + c)) * H * W;

        // ---- load 40x40 img tile (zero outside image) ----
        for (int i = tid; i < IN_DIM * IN_DIM; i += NT) {
            int r = i / IN_DIM, cc = i - r * IN_DIM;
            int gy = y0 - 4 + r, gx = x0 - 4 + cc;
            float v = 0.0f;
            if (gy >= 0 && gy < H && gx >= 0 && gx < W) v = ch[(size_t)gy * W + gx];
            s_in[r][cc] = v;
        }
        __syncthreads();

        // ---- horizontal gaussian: rows 0..39, cols map to x-halo 2 ----
        for (int i = tid; i < IN_DIM * TMP_W; i += NT) {
            int r = i / TMP_W, cc = i - r * TMP_W;
            s_tmp[r][cc] = G0 * (s_in[r][cc] + s_in[r][cc + 4])
                         + G1 * (s_in[r][cc + 1] + s_in[r][cc + 3])
                         + s_in[r][cc + 2];
        }
        __syncthreads();

        // ---- vertical gaussian -> blurred; force 0 outside image (pad semantics) ----
        for (int i = tid; i < BLUR_DIM * BLUR_DIM; i += NT) {
            int r = i / BLUR_DIM, cc = i - r * BLUR_DIM;
            int gy = y0 - 2 + r, gx = x0 - 2 + cc;
            float v = 0.0f;
            if (gy >= 0 && gy < H && gx >= 0 && gx < W) {
                v = G0 * (s_tmp[r][cc] + s_tmp[r + 4][cc])
                  + G1 * (s_tmp[r + 1][cc] + s_tmp[r + 3][cc])
                  + s_tmp[r + 2][cc];
            }
            s_blur[r][cc] = v;
        }
        __syncthreads();

        // ---- sobel + grad magnitude (halo 1), accumulate channels ----
        for (int i = tid; i < GM_DIM * GM_DIM; i += NT) {
            int r = i / GM_DIM, cc = i - r * GM_DIM;
            int gyp = y0 - 1 + r, gxp = x0 - 1 + cc;
            float mag = 0.0f, gxv = 0.0f, gyv = 0.0f;
            if (gyp >= 0 && gyp < H && gxp >= 0 && gxp < W) {
                float t0 = s_blur[r][cc],     t1 = s_blur[r][cc + 1],     t2 = s_blur[r][cc + 2];
                float m0 = s_blur[r + 1][cc],                             m2 = s_blur[r + 1][cc + 2];
                float b0 = s_blur[r + 2][cc], b1 = s_blur[r + 2][cc + 1], b2 = s_blur[r + 2][cc + 2];
                gxv = (t0 - t2) + 2.0f * (m0 - m2) + (b0 - b2);
                gyv = (t0 + 2.0f * t1 + t2) - (b0 + 2.0f * b1 + b2);
                mag = sqrtf(gxv * gxv + gyv * gyv);
            }
            if (c == 0) s_gmag[r][cc] = mag;
            else        s_gmag[r][cc] += mag;
            if (r >= 1 && r <= TS && cc >= 1 && cc <= TS) {
                if (c == 0) { s_sgx[r - 1][cc - 1] = gxv; s_sgy[r - 1][cc - 1] = gyv; }
                else        { s_sgx[r - 1][cc - 1] += gxv; s_sgy[r - 1][cc - 1] += gyv; }
            }
        }
        __syncthreads();
    }

    // ---- orientation quantization + directional NMS + threshold ----
    const float RAD2DEG = 180.0f / 3.14159f;  // matches reference literal
    const int ddy[8] = {0, 1, 1, 1, 0, -1, -1, -1};
    const int ddx[8] = {1, 1, 0, -1, -1, -1, 0, 1};

    for (int i = tid; i < TS * TS; i += NT) {
        int ly = i / TS, lx = i - ly * TS;
        float gm = s_gmag[ly + 1][lx + 1];
        float ang = atan2f(s_sgy[ly][lx], s_sgx[ly][lx]) * RAD2DEG + 180.0f;
        int q = (int)rintf(ang / 45.0f);       // 0..8, half-to-even like jnp.round
        int ip = q & 7;
        int in_ = (q + 4) & 7;
        // dir_f conv == center - neighbor; out-of-image neighbor reads 0 from halo
        float pos = gm - s_gmag[ly + 1 + ddy[ip]][lx + 1 + ddx[ip]];
        float neg = gm - s_gmag[ly + 1 + ddy[in_]][lx + 1 + ddx[in_]];
        float thin = (fminf(pos, neg) > 0.0f) ? gm : 0.0f;
        float res = (thin < 10.0f) ? 0.0f : thin;
        out[((size_t)b * H + (y0 + ly)) * W + (x0 + lx)] = res;
    }
}

extern "C" void kernel_launch(void* const* d_in, const int* in_sizes, int n_in,
                              void* d_out, int out_size)
{
    const float* img = (const float*)d_in[0];
    float* out = (float*)d_out;
    const int H = 512, W = 512;
    int B = in_sizes[0] / (3 * H * W);   // 16
    dim3 grid(W / TS, H / TS, B);
    canny_fused_kernel<<<grid, NT>>>(img, out, H, W);
}

// round 6
// speedup vs baseline: 1.1146x; 1.1146x over previous
#include <cuda_runtime.h>
#include <math.h>

#define TS 32
#define NT 256
#define IN_DIM 40   // TS + 2*4 halo
#define IN_STR 44   // padded stride (16B-aligned rows for float4 stage-A stores)
#define TMP_W 36    // after horizontal gauss (x halo 4 -> 2)
#define BLUR_DIM 36 // y halo 2, x halo 2
#define GM_DIM 34   // grad-mag with halo 1 for NMS

__global__ __launch_bounds__(NT) void canny_fused_kernel(
    const float* __restrict__ img, float* __restrict__ out,
    int H, int W)
{
    __shared__ float s_in[IN_DIM][IN_STR];
    __shared__ float s_tmp[IN_DIM][TMP_W + 1];
    __shared__ float s_blur[BLUR_DIM][BLUR_DIM + 1];
    __shared__ float s_gmag[GM_DIM][GM_DIM + 1];
    __shared__ float s_sgx[TS][TS];
    __shared__ float s_sgy[TS][TS];
    __shared__ int s_noff[8];

    const int tid = threadIdx.x;
    const int x0 = blockIdx.x * TS;
    const int y0 = blockIdx.y * TS;
    const int b  = blockIdx.z;

    // scipy.signal.gaussian(5, std=1): unnormalized, peak 1 (R1 literals, verbatim)
    const float G0 = 0.13533528f;   // exp(-2)
    const float G1 = 0.60653067f;   // exp(-0.5)

    if (tid < 8) {
        const int ddy[8] = {0, 1, 1, 1, 0, -1, -1, -1};
        const int ddx[8] = {1, 1, 0, -1, -1, -1, 0, 1};
        s_noff[tid] = ddy[tid] * (GM_DIM + 1) + ddx[tid];
    }

    // per-stage 2D decompositions (one div/mod per thread per stage)
    const int txB = tid % TMP_W,    tyB = tid / TMP_W;    // 36 cols, ty 0..7 (tid<252)
    const int txD = tid % GM_DIM,   tyD = tid / GM_DIM;   // 34 cols, ty 0..7 (tid<238)

    const bool interior = (x0 >= 32) && (x0 <= 448) && (y0 >= 32) && (y0 <= 448);

    for (int c = 0; c < 3; ++c) {
        const float* ch = img + ((size_t)(b * 3 + c)) * H * W;

        // ---- stage A: load 40x40 img tile ----
        if (interior) {
            // pure data movement, float4 (rows 16B-aligned: (x0-4)*4 % 16 == 0)
            for (int i = tid; i < IN_DIM * 10; i += NT) {
                int r = i >> 31 ? 0 : (i / 10);          // i/10 once per iter (cheap mulhi)
                int uc = i - r * 10;
                float4 v = *(const float4*)(ch + (size_t)(y0 - 4 + r) * W + (x0 - 4) + 4 * uc);
                *(float4*)(&s_in[r][4 * uc]) = v;
            }
        } else {
            for (int i = tid; i < IN_DIM * IN_DIM; i += NT) {
                int r = i / IN_DIM, cc = i - r * IN_DIM;
                int gy = y0 - 4 + r, gx = x0 - 4 + cc;
                float v = 0.0f;
                if (gy >= 0 && gy < H && gx >= 0 && gx < W) v = ch[(size_t)gy * W + gx];
                s_in[r][cc] = v;
            }
        }
        __syncthreads();

        // ---- stage B: horizontal gaussian (bodies verbatim from R1) ----
        if (tid < 252) {
            int cc = txB;
            for (int r = tyB; r < IN_DIM; r += 7) {
                s_tmp[r][cc] = G0 * (s_in[r][cc] + s_in[r][cc + 4])
                             + G1 * (s_in[r][cc + 1] + s_in[r][cc + 3])
                             + s_in[r][cc + 2];
            }
        }
        __syncthreads();

        // ---- stage C: vertical gaussian -> blurred; 0 outside image ----
        if (tid < 252) {
            int cc = txB;
            for (int r = tyB; r < BLUR_DIM; r += 7) {
                int gy = y0 - 2 + r, gx = x0 - 2 + cc;
                float v = 0.0f;
                if (gy >= 0 && gy < H && gx >= 0 && gx < W) {
                    v = G0 * (s_tmp[r][cc] + s_tmp[r + 4][cc])
                      + G1 * (s_tmp[r + 1][cc] + s_tmp[r + 3][cc])
                      + s_tmp[r + 2][cc];
                }
                s_blur[r][cc] = v;
            }
        }
        __syncthreads();

        // ---- stage D: sobel + grad magnitude, accumulate channels ----
        if (tid < 238) {
            int cc = txD;
            for (int r = tyD; r < GM_DIM; r += 7) {
                int gyp = y0 - 1 + r, gxp = x0 - 1 + cc;
                float mag = 0.0f, gxv = 0.0f, gyv = 0.0f;
                if (gyp >= 0 && gyp < H && gxp >= 0 && gxp < W) {
                    float t0 = s_blur[r][cc],     t1 = s_blur[r][cc + 1],     t2 = s_blur[r][cc + 2];
                    float m0 = s_blur[r + 1][cc],                             m2 = s_blur[r + 1][cc + 2];
                    float b0 = s_blur[r + 2][cc], b1 = s_blur[r + 2][cc + 1], b2 = s_blur[r + 2][cc + 2];
                    gxv = (t0 - t2) + 2.0f * (m0 - m2) + (b0 - b2);
                    gyv = (t0 + 2.0f * t1 + t2) - (b0 + 2.0f * b1 + b2);
                    mag = sqrtf(gxv * gxv + gyv * gyv);
                }
                if (c == 0) s_gmag[r][cc] = mag;
                else        s_gmag[r][cc] += mag;
                if (r >= 1 && r <= TS && cc >= 1 && cc <= TS) {
                    if (c == 0) { s_sgx[r - 1][cc - 1] = gxv; s_sgy[r - 1][cc - 1] = gyv; }
                    else        { s_sgx[r - 1][cc - 1] += gxv; s_sgy[r - 1][cc - 1] += gyv; }
                }
            }
        }
        __syncthreads();
    }

    // ---- orientation quantization + directional NMS + threshold (verbatim FP) ----
    const float RAD2DEG = 180.0f / 3.14159f;  // matches reference literal
    const float* gmag_flat = &s_gmag[0][0];

    for (int i = tid; i < TS * TS; i += NT) {
        int ly = i >> 5, lx = i & 31;
        float gm = s_gmag[ly + 1][lx + 1];
        float ang = atan2f(s_sgy[ly][lx], s_sgx[ly][lx]) * RAD2DEG + 180.0f;
        int q = (int)rintf(ang / 45.0f);       // 0..8, half-to-even like jnp.round
        int ip = q & 7;
        int in_ = (q + 4) & 7;
        int ci = (ly + 1) * (GM_DIM + 1) + (lx + 1);
        float pos = gm - gmag_flat[ci + s_noff[ip]];
        float neg = gm - gmag_flat[ci + s_noff[in_]];
        float thin = (fminf(pos, neg) > 0.0f) ? gm : 0.0f;
        float res = (thin < 10.0f) ? 0.0f : thin;
        out[((size_t)b * H + (y0 + ly)) * W + (x0 + lx)] = res;
    }
}

extern "C" void kernel_launch(void* const* d_in, const int* in_sizes, int n_in,
                              void* d_out, int out_size)
{
    const float* img = (const float*)d_in[0];
    float* out = (float*)d_out;
    const int H = 512, W = 512;
    int B = in_sizes[0] / (3 * H * W);   // 16
    dim3 grid(W / TS, H / TS, B);
    canny_fused_kernel<<<grid, NT>>>(img, out, H, W);
}

// round 7
// speedup vs baseline: 1.2432x; 1.1154x over previous
#include <cuda_runtime.h>
#include <math.h>

#define TS 32
#define NT 256
#define IN_DIM 40   // TS + 2*4 halo
#define IN_STR 44   // padded stride (16B-aligned rows for float4 stage-A stores)
#define TMP_W 36    // after horizontal gauss (x halo 4 -> 2)
#define BLUR_DIM 36 // y halo 2, x halo 2
#define GM_DIM 34   // grad-mag with halo 1 for NMS

__global__ __launch_bounds__(NT) void canny_fused_kernel(
    const float* __restrict__ img, float* __restrict__ out,
    int H, int W)
{
    __shared__ float s_in[IN_DIM][IN_STR];
    __shared__ float s_tmp[IN_DIM][TMP_W + 1];
    __shared__ float s_blur[BLUR_DIM][BLUR_DIM + 1];
    __shared__ float s_gmag[GM_DIM][GM_DIM + 1];
    __shared__ int s_noff[8];

    const int tid = threadIdx.x;
    const int x0 = blockIdx.x * TS;
    const int y0 = blockIdx.y * TS;
    const int b  = blockIdx.z;

    // scipy.signal.gaussian(5, std=1): unnormalized, peak 1 (R1 literals, verbatim)
    const float G0 = 0.13533528f;   // exp(-2)
    const float G1 = 0.60653067f;   // exp(-0.5)

    if (tid < 8) {
        const int ddy[8] = {0, 1, 1, 1, 0, -1, -1, -1};
        const int ddx[8] = {1, 1, 0, -1, -1, -1, 0, 1};
        s_noff[tid] = ddy[tid] * (GM_DIM + 1) + ddx[tid];
    }

    // per-stage 2D decompositions (one div/mod per thread)
    const int txB = tid % TMP_W,    tyB = tid / TMP_W;    // 36 cols, ty 0..7 (tid<252)
    const int txD = tid % GM_DIM,   tyD = tid / GM_DIM;   // 34 cols, ty 0..6 (tid<238)
    const int r0  = tyD * 5;                               // owned rows r0..min(r0+5,34)
    const int rend = (r0 + 5 < GM_DIM) ? (r0 + 5) : GM_DIM;

    const bool interior = (x0 >= 32) && (x0 <= 448) && (y0 >= 32) && (y0 <= 448);

    // per-thread channel accumulators (register-resident across the c-loop)
    float amag[5], agx[5], agy[5];

    for (int c = 0; c < 3; ++c) {
        const float* ch = img + ((size_t)(b * 3 + c)) * H * W;

        // ---- stage A: load 40x40 img tile ----
        if (interior) {
            // pure data movement, float4 (rows 16B-aligned: (x0-4)*4 % 16 == 0)
            for (int i = tid; i < IN_DIM * 10; i += NT) {
                int r = i / 10, uc = i - r * 10;
                float4 v = *(const float4*)(ch + (size_t)(y0 - 4 + r) * W + (x0 - 4) + 4 * uc);
                *(float4*)(&s_in[r][4 * uc]) = v;
            }
        } else {
            for (int i = tid; i < IN_DIM * IN_DIM; i += NT) {
                int r = i / IN_DIM, cc = i - r * IN_DIM;
                int gy = y0 - 4 + r, gx = x0 - 4 + cc;
                float v = 0.0f;
                if (gy >= 0 && gy < H && gx >= 0 && gx < W) v = ch[(size_t)gy * W + gx];
                s_in[r][cc] = v;
            }
        }
        __syncthreads();

        // ---- stage B: horizontal gaussian (body verbatim) ----
        if (tid < 252) {
            int cc = txB;
            for (int r = tyB; r < IN_DIM; r += 7) {
                s_tmp[r][cc] = G0 * (s_in[r][cc] + s_in[r][cc + 4])
                             + G1 * (s_in[r][cc + 1] + s_in[r][cc + 3])
                             + s_in[r][cc + 2];
            }
        }
        __syncthreads();

        // ---- stage C: vertical gaussian -> blurred; 0 outside image (body verbatim) ----
        if (tid < 252) {
            int cc = txB;
            for (int r = tyB; r < BLUR_DIM; r += 7) {
                int gy = y0 - 2 + r, gx = x0 - 2 + cc;
                float v = 0.0f;
                if (gy >= 0 && gy < H && gx >= 0 && gx < W) {
                    v = G0 * (s_tmp[r][cc] + s_tmp[r + 4][cc])
                      + G1 * (s_tmp[r + 1][cc] + s_tmp[r + 3][cc])
                      + s_tmp[r + 2][cc];
                }
                s_blur[r][cc] = v;
            }
        }
        __syncthreads();

        // ---- stage D: sobel + grad magnitude, rolling 3x3 window, register accumulate ----
        if (tid < 238) {
            int cc = txD;
            float t0 = s_blur[r0][cc],     t1 = s_blur[r0][cc + 1],     t2 = s_blur[r0][cc + 2];
            float m0 = s_blur[r0 + 1][cc], m1 = s_blur[r0 + 1][cc + 1], m2 = s_blur[r0 + 1][cc + 2];
            #pragma unroll
            for (int k = 0; k < 5; ++k) {
                int r = r0 + k;
                if (r < rend) {
                    float b0 = s_blur[r + 2][cc], b1 = s_blur[r + 2][cc + 1], b2 = s_blur[r + 2][cc + 2];
                    int gyp = y0 - 1 + r, gxp = x0 - 1 + cc;
                    float mag = 0.0f, gxv = 0.0f, gyv = 0.0f;
                    if (gyp >= 0 && gyp < H && gxp >= 0 && gxp < W) {
                        gxv = (t0 - t2) + 2.0f * (m0 - m2) + (b0 - b2);
                        gyv = (t0 + 2.0f * t1 + t2) - (b0 + 2.0f * b1 + b2);
                        mag = sqrtf(gxv * gxv + gyv * gyv);
                    }
                    if (c == 0) { amag[k] = mag;  agx[k] = gxv;  agy[k] = gyv; }
                    else        { amag[k] += mag; agx[k] += gxv; agy[k] += gyv; }
                    t0 = m0; t1 = m1; t2 = m2;
                    m0 = b0; m1 = b1; m2 = b2;
                }
            }
        }
        __syncthreads();   // s_blur overwritten by next channel's stage C
    }

    // ---- write summed grad-mag for neighbor gathers ----
    if (tid < 238) {
        int cc = txD;
        #pragma unroll
        for (int k = 0; k < 5; ++k) {
            int r = r0 + k;
            if (r < rend) s_gmag[r][cc] = amag[k];
        }
    }
    __syncthreads();

    // ---- orientation quantization + directional NMS + threshold (FP verbatim) ----
    const float RAD2DEG = 180.0f / 3.14159f;  // matches reference literal
    const float* gmag_flat = &s_gmag[0][0];

    if (tid < 238) {
        int cc = txD;
        #pragma unroll
        for (int k = 0; k < 5; ++k) {
            int r = r0 + k;
            if (r < rend && r >= 1 && r <= TS && cc >= 1 && cc <= TS) {
                float gm = amag[k];
                float ang = atan2f(agy[k], agx[k]) * RAD2DEG + 180.0f;
                int q = (int)rintf(ang / 45.0f);       // 0..8, half-to-even like jnp.round
                int ip = q & 7;
                int in_ = (q + 4) & 7;
                int ci = r * (GM_DIM + 1) + cc;
                float pos = gm - gmag_flat[ci + s_noff[ip]];
                float neg = gm - gmag_flat[ci + s_noff[in_]];
                float thin = (fminf(pos, neg) > 0.0f) ? gm : 0.0f;
                float res = (thin < 10.0f) ? 0.0f : thin;
                out[((size_t)b * H + (y0 + r - 1)) * W + (x0 + cc - 1)] = res;
            }
        }
    }
}

extern "C" void kernel_launch(void* const* d_in, const int* in_sizes, int n_in,
                              void* d_out, int out_size)
{
    const float* img = (const float*)d_in[0];
    float* out = (float*)d_out;
    const int H = 512, W = 512;
    int B = in_sizes[0] / (3 * H * W);   // 16
    dim3 grid(W / TS, H / TS, B);
    canny_fused_kernel<<<grid, NT>>>(img, out, H, W);
}

// round 9
// speedup vs baseline: 1.4724x; 1.1844x over previous
#include <cuda_runtime.h>
#include <math.h>

#define TS 32
#define NT 256
#define IN_DIM 40   // TS + 2*4 halo
#define IN_STR 44   // padded stride (16B-aligned rows for float4 stage-A stores)
#define TMP_W 36    // after horizontal gauss (x halo 4 -> 2)
#define BLUR_DIM 36 // y halo 2, x halo 2
#define GM_DIM 34   // grad-mag with halo 1 for NMS

__global__ __launch_bounds__(NT) void canny_fused_kernel(
    const float* __restrict__ img, float* __restrict__ out,
    int H, int W)
{
    __shared__ float s_in[IN_DIM][IN_STR];
    __shared__ float s_tmp[IN_DIM][TMP_W + 1];
    __shared__ float s_blur[BLUR_DIM][BLUR_DIM + 1];
    __shared__ float s_gmag[GM_DIM][GM_DIM + 1];
    __shared__ int s_noff[8];

    const int tid = threadIdx.x;
    const int x0 = blockIdx.x * TS;
    const int y0 = blockIdx.y * TS;
    const int b  = blockIdx.z;

    // scipy.signal.gaussian(5, std=1): unnormalized, peak 1 (R1 literals, verbatim)
    const float G0 = 0.13533528f;   // exp(-2)
    const float G1 = 0.60653067f;   // exp(-0.5)

    if (tid < 8) {
        const int ddy[8] = {0, 1, 1, 1, 0, -1, -1, -1};
        const int ddx[8] = {1, 1, 0, -1, -1, -1, 0, 1};
        s_noff[tid] = ddy[tid] * (GM_DIM + 1) + ddx[tid];
    }

    // stage B mapping: 240 threads, one row x 6-wide x-segment each
    const int tB_r = tid / 6, tB_c0 = (tid - tB_r * 6) * 6;     // row 0..39, col0 in {0,6,..,30}
    // stage C mapping: 216 threads, one column x 6-tall y-segment each
    const int tC_rs = tid / 36, tC_c = tid - tC_rs * 36;        // rs 0..6(use<6), col 0..35
    const int tC_r0 = tC_rs * 6;
    // stage D mapping: 238 threads, one column x 5-tall segment each
    const int tD_ty = tid / GM_DIM, tD_c = tid - tD_ty * GM_DIM; // ty 0..6, col 0..33
    const int r0  = tD_ty * 5;
    const int rend = (r0 + 5 < GM_DIM) ? (r0 + 5) : GM_DIM;

    const bool interior = (x0 >= 32) && (x0 <= 448) && (y0 >= 32) && (y0 <= 448);

    // per-thread channel accumulators (register-resident across the c-loop)
    float amag[5], agx[5], agy[5];

    for (int c = 0; c < 3; ++c) {
        const float* ch = img + ((size_t)(b * 3 + c)) * H * W;

        // ---- stage A: load 40x40 img tile ----
        if (interior) {
            // pure data movement, float4 (rows 16B-aligned: (x0-4)*4 % 16 == 0)
            for (int i = tid; i < IN_DIM * 10; i += NT) {
                int r = i / 10, uc = i - r * 10;
                float4 v = *(const float4*)(ch + (size_t)(y0 - 4 + r) * W + (x0 - 4) + 4 * uc);
                *(float4*)(&s_in[r][4 * uc]) = v;
            }
        } else {
            for (int i = tid; i < IN_DIM * IN_DIM; i += NT) {
                int r = i / IN_DIM, cc = i - r * IN_DIM;
                int gy = y0 - 4 + r, gx = x0 - 4 + cc;
                float v = 0.0f;
                if (gy >= 0 && gy < H && gx >= 0 && gx < W) v = ch[(size_t)gy * W + gx];
                s_in[r][cc] = v;
            }
        }
        __syncthreads();

        // ---- stage B: horizontal gaussian, rolling 5-tap window along x ----
        // gauss pinned to contraction (A): fmul(G1,·) -> fma(G0,·,·) -> fadd(+center)
        if (tid < 240) {
            int r = tB_r;
            float w0 = s_in[r][tB_c0],     w1 = s_in[r][tB_c0 + 1], w2 = s_in[r][tB_c0 + 2];
            float w3 = s_in[r][tB_c0 + 3], w4 = s_in[r][tB_c0 + 4];
            #pragma unroll
            for (int j = 0; j < 6; ++j) {
                int cc = tB_c0 + j;
                float f1 = __fadd_rn(w0, w4);
                float f2 = __fadd_rn(w1, w3);
                s_tmp[r][cc] = __fadd_rn(__fmaf_rn(G0, f1, __fmul_rn(G1, f2)), w2);
                if (j < 5) {
                    float wn = s_in[r][cc + 5];
                    w0 = w1; w1 = w2; w2 = w3; w3 = w4; w4 = wn;
                }
            }
        }
        __syncthreads();

        // ---- stage C: vertical gaussian, rolling 5-tap window along y; 0 outside image ----
        if (tid < 216) {
            int cc = tC_c;
            float w0 = s_tmp[tC_r0][cc],     w1 = s_tmp[tC_r0 + 1][cc], w2 = s_tmp[tC_r0 + 2][cc];
            float w3 = s_tmp[tC_r0 + 3][cc], w4 = s_tmp[tC_r0 + 4][cc];
            #pragma unroll
            for (int j = 0; j < 6; ++j) {
                int r = tC_r0 + j;
                int gy = y0 - 2 + r, gx = x0 - 2 + cc;
                float v = 0.0f;
                if (gy >= 0 && gy < H && gx >= 0 && gx < W) {
                    float f1 = __fadd_rn(w0, w4);
                    float f2 = __fadd_rn(w1, w3);
                    v = __fadd_rn(__fmaf_rn(G0, f1, __fmul_rn(G1, f2)), w2);
                }
                s_blur[r][cc] = v;
                if (j < 5) {
                    float wn = s_tmp[r + 5][cc];
                    w0 = w1; w1 = w2; w2 = w3; w3 = w4; w4 = wn;
                }
            }
        }
        __syncthreads();

        // ---- stage D: sobel + grad magnitude, rolling 3x3 window, register accumulate ----
        // (verbatim from R7 passing binary — proven value-safe)
        if (tid < 238) {
            int cc = tD_c;
            float t0 = s_blur[r0][cc],     t1 = s_blur[r0][cc + 1],     t2 = s_blur[r0][cc + 2];
            float m0 = s_blur[r0 + 1][cc], m1 = s_blur[r0 + 1][cc + 1], m2 = s_blur[r0 + 1][cc + 2];
            #pragma unroll
            for (int k = 0; k < 5; ++k) {
                int r = r0 + k;
                if (r < rend) {
                    float b0 = s_blur[r + 2][cc], b1 = s_blur[r + 2][cc + 1], b2 = s_blur[r + 2][cc + 2];
                    int gyp = y0 - 1 + r, gxp = x0 - 1 + cc;
                    float mag = 0.0f, gxv = 0.0f, gyv = 0.0f;
                    if (gyp >= 0 && gyp < H && gxp >= 0 && gxp < W) {
                        gxv = (t0 - t2) + 2.0f * (m0 - m2) + (b0 - b2);
                        gyv = (t0 + 2.0f * t1 + t2) - (b0 + 2.0f * b1 + b2);
                        mag = sqrtf(gxv * gxv + gyv * gyv);
                    }
                    if (c == 0) { amag[k] = mag;  agx[k] = gxv;  agy[k] = gyv; }
                    else        { amag[k] += mag; agx[k] += gxv; agy[k] += gyv; }
                    t0 = m0; t1 = m1; t2 = m2;
                    m0 = b0; m1 = b1; m2 = b2;
                }
            }
        }
        __syncthreads();   // s_blur overwritten by next channel's stage C
    }

    // ---- write summed grad-mag for neighbor gathers ----
    if (tid < 238) {
        int cc = tD_c;
        #pragma unroll
        for (int k = 0; k < 5; ++k) {
            int r = r0 + k;
            if (r < rend) s_gmag[r][cc] = amag[k];
        }
    }
    __syncthreads();

    // ---- orientation quantization + directional NMS + threshold (FP verbatim) ----
    const float RAD2DEG = 180.0f / 3.14159f;  // matches reference literal
    const float* gmag_flat = &s_gmag[0][0];

    if (tid < 238) {
        int cc = tD_c;
        #pragma unroll
        for (int k = 0; k < 5; ++k) {
            int r = r0 + k;
            if (r < rend && r >= 1 && r <= TS && cc >= 1 && cc <= TS) {
                float gm = amag[k];
                float ang = atan2f(agy[k], agx[k]) * RAD2DEG + 180.0f;
                int q = (int)rintf(ang / 45.0f);       // 0..8, half-to-even like jnp.round
                int ip = q & 7;
                int in_ = (q + 4) & 7;
                int ci = r * (GM_DIM + 1) + cc;
                float pos = gm - gmag_flat[ci + s_noff[ip]];
                float neg = gm - gmag_flat[ci + s_noff[in_]];
                float thin = (fminf(pos, neg) > 0.0f) ? gm : 0.0f;
                float res = (thin < 10.0f) ? 0.0f : thin;
                out[((size_t)b * H + (y0 + r - 1)) * W + (x0 + cc - 1)] = res;
            }
        }
    }
}

extern "C" void kernel_launch(void* const* d_in, const int* in_sizes, int n_in,
                              void* d_out, int out_size)
{
    const float* img = (const float*)d_in[0];
    float* out = (float*)d_out;
    const int H = 512, W = 512;
    int B = in_sizes[0] / (3 * H * W);   // 16
    dim3 grid(W / TS, H / TS, B);
    canny_fused_kernel<<<grid, NT>>>(img, out, H, W);
}